// round 1
// baseline (speedup 1.0000x reference)
#include <cuda_runtime.h>
#include <math.h>

#define NB 64
#define NP 16800
#define NO 64
#define NCH 66               // ceil(NP/256)
#define NBLK_D (NB*NCH)      // 4224
#define THRESH 0.35f
#define NEGPOS 7

// ---------------- static device scratch ----------------
__device__ float g_bto[(size_t)NB*NP];       // best_truth_overlap
__device__ int   g_bti[(size_t)NB*NP];       // best_truth_idx
__device__ float g_lc [(size_t)NB*NP];       // loss_c / ce per (b,p)
__device__ unsigned char g_posm[(size_t)NB*NP];
__device__ float g_bpo[NB*NO];               // best_prior_overlap
__device__ int   g_bpi[NB*NO];               // best_prior_idx
__device__ float g_part_l [NBLK_D];
__device__ float g_part_lm[NBLK_D];
__device__ int   g_numpos[NB];
__device__ int   g_np1_tot;
__device__ float g_lossc_b[NB];

__device__ __forceinline__ float sl1(float x){
    float a = fabsf(x);
    return (a < 1.f) ? 0.5f*a*a : a - 0.5f;
}
__device__ __forceinline__ unsigned fmap(float f){
    unsigned u = __float_as_uint(f);
    return (u & 0x80000000u) ? ~u : (u | 0x80000000u);
}

// ---------------- init ----------------
__global__ void kInit(){
    int i = threadIdx.x;
    if (i < NB) g_numpos[i] = 0;
    if (i == 0) g_np1_tot = 0;
}

// ---------------- kernel A: per (b,p) best truth ----------------
__global__ void kA(const float* __restrict__ targets, const float* __restrict__ priors){
    int b = blockIdx.y;
    int p = blockIdx.x*256 + threadIdx.x;
    __shared__ float st[NO][4];
    __shared__ float sta[NO];
    int tid = threadIdx.x;
    if (tid < NO){
        const float* tr = targets + ((size_t)b*NO + tid)*15;
        float x1=tr[0], y1=tr[1], x2=tr[2], y2=tr[3];
        st[tid][0]=x1; st[tid][1]=y1; st[tid][2]=x2; st[tid][3]=y2;
        sta[tid] = (x2-x1)*(y2-y1);
    }
    __syncthreads();
    if (p >= NP) return;
    float pcx=priors[p*4+0], pcy=priors[p*4+1], pw=priors[p*4+2], ph=priors[p*4+3];
    float px1=pcx-pw*0.5f, py1=pcy-ph*0.5f, px2=pcx+pw*0.5f, py2=pcy+ph*0.5f;
    float pa = (px2-px1)*(py2-py1);
    float best = -1.f; int bidx = 0;
    #pragma unroll 8
    for (int t=0; t<NO; ++t){
        float lx=fmaxf(st[t][0],px1), ly=fmaxf(st[t][1],py1);
        float rx=fminf(st[t][2],px2), ry=fminf(st[t][3],py2);
        float w=fmaxf(rx-lx,0.f), h=fmaxf(ry-ly,0.f);
        float inter = w*h;
        float v = inter / (sta[t] + pa - inter);
        if (v > best){ best = v; bidx = t; }   // strict > keeps first argmax
    }
    size_t ip = (size_t)b*NP + p;
    g_bto[ip] = best;
    g_bti[ip] = bidx;
}

// ---------------- kernel B: per (b,t) best prior ----------------
__global__ void kB(const float* __restrict__ targets, const float* __restrict__ priors){
    int t = blockIdx.x, b = blockIdx.y, tid = threadIdx.x;
    const float* tr = targets + ((size_t)b*NO + t)*15;
    float x1=tr[0], y1=tr[1], x2=tr[2], y2=tr[3];
    float ta = (x2-x1)*(y2-y1);
    float best = -1.f; int bidx = 0x7fffffff;
    for (int p = tid; p < NP; p += 256){
        float pcx=priors[p*4+0], pcy=priors[p*4+1], pw=priors[p*4+2], ph=priors[p*4+3];
        float px1=pcx-pw*0.5f, py1=pcy-ph*0.5f, px2=pcx+pw*0.5f, py2=pcy+ph*0.5f;
        float pa = (px2-px1)*(py2-py1);
        float lx=fmaxf(x1,px1), ly=fmaxf(y1,py1);
        float rx=fminf(x2,px2), ry=fminf(y2,py2);
        float w=fmaxf(rx-lx,0.f), h=fmaxf(ry-ly,0.f);
        float inter = w*h;
        float v = inter / (ta + pa - inter);
        if (v > best){ best = v; bidx = p; }   // per-thread first max (p increasing)
    }
    __shared__ float rv[256];
    __shared__ int   ri[256];
    rv[tid]=best; ri[tid]=bidx; __syncthreads();
    for (int s=128; s>0; s>>=1){
        if (tid < s){
            if (rv[tid+s] > rv[tid] || (rv[tid+s]==rv[tid] && ri[tid+s] < ri[tid])){
                rv[tid]=rv[tid+s]; ri[tid]=ri[tid+s];
            }
        }
        __syncthreads();
    }
    if (tid==0){ g_bpo[b*NO+t]=rv[0]; g_bpi[b*NO+t]=ri[0]; }
}

// ---------------- kernel C: sequential scatter (last write wins) ----------------
__global__ void kC(){
    int b = threadIdx.x;
    if (b >= NB) return;
    int   pidx[NO];
    float origv[NO];
    bool  val[NO];
    for (int j=0; j<NO; ++j){
        pidx[j]  = g_bpi[b*NO+j];
        val[j]   = (g_bpo[b*NO+j] >= 0.2f);
        origv[j] = g_bto[(size_t)b*NP + pidx[j]];   // pre-scatter values
    }
    for (int j=0; j<NO; ++j){
        g_bti[(size_t)b*NP + pidx[j]] = j;
        g_bto[(size_t)b*NP + pidx[j]] = val[j] ? 2.0f : origv[j];
    }
}

// ---------------- kernel D: per (b,p) losses + ce ----------------
__global__ void kD(const float* __restrict__ loc, const float* __restrict__ conf,
                   const float* __restrict__ landm, const float* __restrict__ priors,
                   const float* __restrict__ targets){
    int b = blockIdx.y;
    int p = blockIdx.x*256 + threadIdx.x;
    int tid = threadIdx.x;
    float ll=0.f, llm=0.f; int cp=0, cp1=0;
    if (p < NP){
        size_t ip = (size_t)b*NP + p;
        int   t   = g_bti[ip];
        float bto = g_bto[ip];
        const float* tr = targets + ((size_t)b*NO + t)*15;
        float label = tr[14];
        float cf = (bto < THRESH) ? 0.f : label;
        bool pos  = (cf != 0.f);
        bool pos1 = (cf > 0.f);
        float c0 = conf[ip*2+0], c1 = conf[ip*2+1];
        float m = fmaxf(c0,c1);
        float lse = m + logf(expf(c0-m) + expf(c1-m));
        float lc = lse - (pos ? c1 : c0);
        g_lc[ip]   = lc;
        g_posm[ip] = pos ? 1 : 0;
        if (pos){
            cp = 1;
            float pcx=priors[p*4+0], pcy=priors[p*4+1], pw=priors[p*4+2], ph=priors[p*4+3];
            float x1=tr[0], y1=tr[1], x2=tr[2], y2=tr[3];
            float gcx = ((x1+x2)*0.5f - pcx) / (0.1f*pw);
            float gcy = ((y1+y2)*0.5f - pcy) / (0.1f*ph);
            float gw  = logf((x2-x1)/pw) / 0.2f;
            float gh  = logf((y2-y1)/ph) / 0.2f;
            const float* lr = loc + ip*4;
            ll = sl1(lr[0]-gcx) + sl1(lr[1]-gcy) + sl1(lr[2]-gw) + sl1(lr[3]-gh);
            if (pos1){
                cp1 = 1;
                const float* ld = landm + ip*10;
                #pragma unroll
                for (int i=0;i<5;++i){
                    float gx = (tr[4+2*i] - pcx)/(0.1f*pw);
                    float gy = (tr[5+2*i] - pcy)/(0.1f*ph);
                    llm += sl1(ld[2*i]-gx) + sl1(ld[2*i+1]-gy);
                }
            }
        }
    }
    __shared__ float red[256];
    red[tid]=ll; __syncthreads();
    for (int s=128;s>0;s>>=1){ if(tid<s) red[tid]+=red[tid+s]; __syncthreads(); }
    if (tid==0) g_part_l[blockIdx.y*NCH + blockIdx.x] = red[0];
    __syncthreads();
    red[tid]=llm; __syncthreads();
    for (int s=128;s>0;s>>=1){ if(tid<s) red[tid]+=red[tid+s]; __syncthreads(); }
    if (tid==0) g_part_lm[blockIdx.y*NCH + blockIdx.x] = red[0];
    __syncthreads();
    __shared__ int ired[256];
    ired[tid]=cp; __syncthreads();
    for (int s=128;s>0;s>>=1){ if(tid<s) ired[tid]+=ired[tid+s]; __syncthreads(); }
    if (tid==0) atomicAdd(&g_numpos[b], ired[0]);
    __syncthreads();
    ired[tid]=cp1; __syncthreads();
    for (int s=128;s>0;s>>=1){ if(tid<s) ired[tid]+=ired[tid+s]; __syncthreads(); }
    if (tid==0) atomicAdd(&g_np1_tot, ired[0]);
}

// ---------------- kernel E: radix top-K select + masked sum ----------------
__global__ void kE(){
    int b = blockIdx.x, tid = threadIdx.x;
    __shared__ int hist[256];
    __shared__ unsigned s_prefix, s_pmask;
    __shared__ int s_k, s_cgt;
    int npos = g_numpos[b];
    int K = NEGPOS*npos; if (K > NP-1) K = NP-1;
    const float* lcrow = g_lc + (size_t)b*NP;
    if (tid==0){ s_prefix=0u; s_pmask=0u; s_k=K; s_cgt=0; }
    __syncthreads();
    if (K > 0){
        for (int level=3; level>=0; --level){
            hist[tid]=0; __syncthreads();
            unsigned pm=s_pmask, pf=s_prefix;
            for (int i=tid; i<NP; i+=256){
                unsigned u = fmap(lcrow[i]);
                if ((u & pm) == pf) atomicAdd(&hist[(u >> (level*8)) & 0xFF], 1);
            }
            __syncthreads();
            if (tid==0){
                int k=s_k, cum=0, bin=255;
                for (; bin>0; --bin){
                    int c = hist[bin];
                    if (cum + c >= k) break;
                    cum += c;
                }
                s_cgt += cum;
                s_k = k - cum;
                s_prefix = pf | ((unsigned)bin << (level*8));
                s_pmask  = pm | (0xFFu << (level*8));
            }
            __syncthreads();
        }
    }
    unsigned v = s_prefix;
    int extra = K - s_cgt;
    // stable inclusion among ties: contiguous chunks + exclusive scan of tie counts
    const int chunk = (NP + 255)/256;
    int beg = tid*chunk;
    int end = beg + chunk; if (end > NP) end = NP;
    __shared__ int eqc[256];
    int eq = 0;
    if (K > 0) for (int i=beg;i<end;++i) if (fmap(lcrow[i])==v) eq++;
    eqc[tid]=eq; __syncthreads();
    if (tid==0){ int acc=0; for (int i=0;i<256;++i){ int tmp=eqc[i]; eqc[i]=acc; acc+=tmp; } }
    __syncthreads();
    int run = eqc[tid];
    const unsigned char* posrow = g_posm + (size_t)b*NP;
    float s = 0.f;
    for (int i=beg; i<end; ++i){
        float lv = lcrow[i];
        bool inc = (posrow[i] != 0);
        if (K > 0){
            unsigned u = fmap(lv);
            if (u > v) inc = true;
            else if (u == v){ if (run < extra) inc = true; run++; }
        }
        if (inc) s += lv;
    }
    __shared__ float red[256];
    red[tid]=s; __syncthreads();
    for (int st=128; st>0; st>>=1){ if(tid<st) red[tid]+=red[tid+st]; __syncthreads(); }
    if (tid==0) g_lossc_b[b] = red[0];
}

// ---------------- kernel F: final deterministic reductions ----------------
__global__ void kF(float* __restrict__ out, int out_size){
    int tid = threadIdx.x;
    __shared__ float red[256];
    __shared__ int  ired[256];
    __shared__ float s_ll, s_lm, s_lcf;
    float s = 0.f;
    for (int i=tid; i<NBLK_D; i+=256) s += g_part_l[i];
    red[tid]=s; __syncthreads();
    for (int st=128;st>0;st>>=1){ if(tid<st) red[tid]+=red[tid+st]; __syncthreads(); }
    if (tid==0) s_ll = red[0];
    __syncthreads();
    s = 0.f;
    for (int i=tid; i<NBLK_D; i+=256) s += g_part_lm[i];
    red[tid]=s; __syncthreads();
    for (int st=128;st>0;st>>=1){ if(tid<st) red[tid]+=red[tid+st]; __syncthreads(); }
    if (tid==0) s_lm = red[0];
    __syncthreads();
    s = 0.f;
    if (tid < NB) s = g_lossc_b[tid];
    red[tid]=s; __syncthreads();
    for (int st=128;st>0;st>>=1){ if(tid<st) red[tid]+=red[tid+st]; __syncthreads(); }
    if (tid==0) s_lcf = red[0];
    __syncthreads();
    int np = 0;
    if (tid < NB) np = g_numpos[tid];
    ired[tid]=np; __syncthreads();
    for (int st=128;st>0;st>>=1){ if(tid<st) ired[tid]+=ired[tid+st]; __syncthreads(); }
    if (tid==0){
        float N  = fmaxf((float)ired[0], 1.f);
        float N1 = fmaxf((float)g_np1_tot, 1.f);
        if (out_size > 0) out[0] = s_ll  / N;
        if (out_size > 1) out[1] = s_lcf / N;
        if (out_size > 2) out[2] = s_lm  / N1;
    }
}

extern "C" void kernel_launch(void* const* d_in, const int* in_sizes, int n_in,
                              void* d_out, int out_size){
    const float* loc     = (const float*)d_in[0];
    const float* conf    = (const float*)d_in[1];
    const float* landm   = (const float*)d_in[2];
    const float* priors  = (const float*)d_in[3];
    const float* targets = (const float*)d_in[4];
    float* out = (float*)d_out;

    kInit<<<1,64>>>();
    kA<<<dim3(NCH,NB),256>>>(targets, priors);
    kB<<<dim3(NO,NB),256>>>(targets, priors);
    kC<<<1,64>>>();
    kD<<<dim3(NCH,NB),256>>>(loc, conf, landm, priors, targets);
    kE<<<NB,256>>>();
    kF<<<1,256>>>(out, out_size);
}

// round 2
// speedup vs baseline: 1.5645x; 1.5645x over previous
#include <cuda_runtime.h>
#include <math.h>

#define NB 64
#define NP 16800
#define NO 64
#define NCH 66               // ceil(NP/256)
#define NBLK_D (NB*NCH)      // 4224
#define THRESH 0.35f
#define NEGPOS 7

// ---------------- static device scratch ----------------
__device__ float g_bto[(size_t)NB*NP];       // best_truth_overlap
__device__ int   g_bti[(size_t)NB*NP];       // best_truth_idx
__device__ float g_lc [(size_t)NB*NP];       // loss_c / ce per (b,p)
__device__ unsigned char g_posm[(size_t)NB*NP];
__device__ unsigned long long g_bpkey[NB*NO]; // packed (fbits(best_prior_overlap)<<32)|~p
__device__ float g_part_l [NBLK_D];
__device__ float g_part_lm[NBLK_D];
__device__ int   g_numpos[NB];
__device__ int   g_np1_tot;
__device__ float g_lossc_b[NB];

__device__ __forceinline__ float sl1(float x){
    float a = fabsf(x);
    return (a < 1.f) ? 0.5f*a*a : a - 0.5f;
}
__device__ __forceinline__ unsigned fmap(float f){
    unsigned u = __float_as_uint(f);
    return (u & 0x80000000u) ? ~u : (u | 0x80000000u);
}

// ---------------- init ----------------
__global__ void kInit(){
    int i = blockIdx.x*256 + threadIdx.x;
    if (i < NB*NO) g_bpkey[i] = 0ull;
    if (i < NB)    g_numpos[i] = 0;
    if (i == 0)    g_np1_tot = 0;
}

// ---------------- fused kernel AB ----------------
// per (b,p): best truth over t (first-max)      -> g_bto/g_bti
// per (b,t): best prior over p (first-max)      -> g_bpkey via warp butterfly + atomicMax
__global__ void kAB(const float* __restrict__ targets, const float* __restrict__ priors){
    int b   = blockIdx.y;
    int tid = threadIdx.x;
    int p   = blockIdx.x*256 + tid;
    bool valid = (p < NP);

    __shared__ float stx1[NO], sty1[NO], stx2[NO], sty2[NO], sta[NO];
    if (tid < NO){
        const float* tr = targets + ((size_t)b*NO + tid)*15;
        float x1=tr[0], y1=tr[1], x2=tr[2], y2=tr[3];
        stx1[tid]=x1; sty1[tid]=y1; stx2[tid]=x2; sty2[tid]=y2;
        sta[tid] = (x2-x1)*(y2-y1);
    }
    __syncthreads();

    float4 pr = ((const float4*)priors)[valid ? p : 0];
    float px1 = pr.x - pr.z*0.5f, py1 = pr.y - pr.w*0.5f;
    float px2 = pr.x + pr.z*0.5f, py2 = pr.y + pr.w*0.5f;
    float pa  = pr.z * pr.w;   // (px2-px1)*(py2-py1) == w*h exactly? compute explicitly to match:
    pa = (px2-px1)*(py2-py1);

    float bestv = -1.f; int bt = 0;
    unsigned long long base = (unsigned long long)b*NO;

    #pragma unroll 4
    for (int t = 0; t < NO; ++t){
        float lx = fmaxf(stx1[t], px1), ly = fmaxf(sty1[t], py1);
        float rx = fminf(stx2[t], px2), ry = fminf(sty2[t], py2);
        float w  = fmaxf(rx-lx, 0.f),   h  = fmaxf(ry-ly, 0.f);
        float inter = w*h;
        float denom = sta[t] + pa - inter;
        float v = valid ? __fdividef(inter, denom) : -1.f;
        if (v > bestv){ bestv = v; bt = t; }        // strict > keeps first (lowest t)
        // warp max over p for this t
        float vm = v;
        #pragma unroll
        for (int o = 16; o > 0; o >>= 1) vm = fmaxf(vm, __shfl_xor_sync(0xffffffffu, vm, o));
        unsigned mk = __ballot_sync(0xffffffffu, v == vm);
        if (((tid & 31) == (__ffs(mk)-1)) && vm >= 0.f){
            unsigned long long key = ((unsigned long long)__float_as_uint(vm) << 32) | (unsigned)(~p);
            atomicMax(&g_bpkey[base + t], key);
        }
    }
    if (valid){
        size_t ip = (size_t)b*NP + p;
        g_bto[ip] = bestv;
        g_bti[ip] = bt;
    }
}

// ---------------- kernel C: parallel last-writer-wins scatter ----------------
// reference: bto.at[bpi].set(where(valid, 2.0, bto[bpi])) -- the non-valid branch
// writes back the ORIGINAL (pre-scatter) value => no-op. Only bti always written.
__global__ void kC(){
    int b = blockIdx.x, j = threadIdx.x;
    __shared__ int sp[NO];
    unsigned long long key = g_bpkey[b*NO + j];
    int   pidx = (int)(~(unsigned)key);
    float bpo  = __uint_as_float((unsigned)(key >> 32));
    sp[j] = pidx;
    __syncthreads();
    bool win = true;
    for (int j2 = j+1; j2 < NO; ++j2) if (sp[j2] == pidx) win = false;
    if (win){
        size_t ip = (size_t)b*NP + pidx;
        g_bti[ip] = j;
        if (bpo >= 0.2f) g_bto[ip] = 2.0f;
    }
}

// ---------------- kernel D: per (b,p) losses + ce ----------------
__global__ void kD(const float* __restrict__ loc, const float* __restrict__ conf,
                   const float* __restrict__ landm, const float* __restrict__ priors,
                   const float* __restrict__ targets){
    int b = blockIdx.y;
    int p = blockIdx.x*256 + threadIdx.x;
    int tid = threadIdx.x;
    float ll=0.f, llm=0.f; int cp=0, cp1=0;
    if (p < NP){
        size_t ip = (size_t)b*NP + p;
        int   t   = g_bti[ip];
        float bto = g_bto[ip];
        const float* tr = targets + ((size_t)b*NO + t)*15;
        float label = tr[14];
        float cf = (bto < THRESH) ? 0.f : label;
        bool pos  = (cf != 0.f);
        bool pos1 = (cf > 0.f);
        float2 c = ((const float2*)conf)[ip];
        float m = fmaxf(c.x, c.y);
        float lse = m + logf(expf(c.x-m) + expf(c.y-m));
        float lc = lse - (pos ? c.y : c.x);
        g_lc[ip]   = lc;
        g_posm[ip] = pos ? 1 : 0;
        if (pos){
            cp = 1;
            float4 pr = ((const float4*)priors)[p];
            float pcx=pr.x, pcy=pr.y, pw=pr.z, ph=pr.w;
            float x1=tr[0], y1=tr[1], x2=tr[2], y2=tr[3];
            float gcx = ((x1+x2)*0.5f - pcx) / (0.1f*pw);
            float gcy = ((y1+y2)*0.5f - pcy) / (0.1f*ph);
            float gw  = logf((x2-x1)/pw) / 0.2f;
            float gh  = logf((y2-y1)/ph) / 0.2f;
            float4 lr = ((const float4*)loc)[ip];
            ll = sl1(lr.x-gcx) + sl1(lr.y-gcy) + sl1(lr.z-gw) + sl1(lr.w-gh);
            if (pos1){
                cp1 = 1;
                const float* ld = landm + ip*10;
                #pragma unroll
                for (int i=0;i<5;++i){
                    float gx = (tr[4+2*i] - pcx)/(0.1f*pw);
                    float gy = (tr[5+2*i] - pcy)/(0.1f*ph);
                    llm += sl1(ld[2*i]-gx) + sl1(ld[2*i+1]-gy);
                }
            }
        }
    }
    __shared__ float red[256];
    red[tid]=ll; __syncthreads();
    for (int s=128;s>0;s>>=1){ if(tid<s) red[tid]+=red[tid+s]; __syncthreads(); }
    if (tid==0) g_part_l[blockIdx.y*NCH + blockIdx.x] = red[0];
    __syncthreads();
    red[tid]=llm; __syncthreads();
    for (int s=128;s>0;s>>=1){ if(tid<s) red[tid]+=red[tid+s]; __syncthreads(); }
    if (tid==0) g_part_lm[blockIdx.y*NCH + blockIdx.x] = red[0];
    __syncthreads();
    __shared__ int ired[256];
    ired[tid]=cp; __syncthreads();
    for (int s=128;s>0;s>>=1){ if(tid<s) ired[tid]+=ired[tid+s]; __syncthreads(); }
    if (tid==0) atomicAdd(&g_numpos[b], ired[0]);
    __syncthreads();
    ired[tid]=cp1; __syncthreads();
    for (int s=128;s>0;s>>=1){ if(tid<s) ired[tid]+=ired[tid+s]; __syncthreads(); }
    if (tid==0) atomicAdd(&g_np1_tot, ired[0]);
}

// ---------------- kernel E: radix top-K select + masked sum ----------------
__global__ void kE(){
    int b = blockIdx.x, tid = threadIdx.x;
    __shared__ int hist[256];
    __shared__ unsigned s_prefix, s_pmask;
    __shared__ int s_k, s_cgt;
    int npos = g_numpos[b];
    int K = NEGPOS*npos; if (K > NP-1) K = NP-1;
    const float* lcrow = g_lc + (size_t)b*NP;
    if (tid==0){ s_prefix=0u; s_pmask=0u; s_k=K; s_cgt=0; }
    __syncthreads();
    if (K > 0){
        for (int level=3; level>=0; --level){
            hist[tid]=0; __syncthreads();
            unsigned pm=s_pmask, pf=s_prefix;
            for (int i=tid; i<NP; i+=256){
                unsigned u = fmap(lcrow[i]);
                if ((u & pm) == pf) atomicAdd(&hist[(u >> (level*8)) & 0xFF], 1);
            }
            __syncthreads();
            if (tid==0){
                int k=s_k, cum=0, bin=255;
                for (; bin>0; --bin){
                    int c = hist[bin];
                    if (cum + c >= k) break;
                    cum += c;
                }
                s_cgt += cum;
                s_k = k - cum;
                s_prefix = pf | ((unsigned)bin << (level*8));
                s_pmask  = pm | (0xFFu << (level*8));
            }
            __syncthreads();
        }
    }
    unsigned v = s_prefix;
    int extra = K - s_cgt;
    const int chunk = (NP + 255)/256;
    int beg = tid*chunk;
    int end = beg + chunk; if (end > NP) end = NP;
    __shared__ int eqc[256];
    int eq = 0;
    if (K > 0) for (int i=beg;i<end;++i) if (fmap(lcrow[i])==v) eq++;
    eqc[tid]=eq; __syncthreads();
    if (tid==0){ int acc=0; for (int i=0;i<256;++i){ int tmp=eqc[i]; eqc[i]=acc; acc+=tmp; } }
    __syncthreads();
    int run = eqc[tid];
    const unsigned char* posrow = g_posm + (size_t)b*NP;
    float s = 0.f;
    for (int i=beg; i<end; ++i){
        float lv = lcrow[i];
        bool inc = (posrow[i] != 0);
        if (K > 0){
            unsigned u = fmap(lv);
            if (u > v) inc = true;
            else if (u == v){ if (run < extra) inc = true; run++; }
        }
        if (inc) s += lv;
    }
    __shared__ float red[256];
    red[tid]=s; __syncthreads();
    for (int st=128; st>0; st>>=1){ if(tid<st) red[tid]+=red[tid+st]; __syncthreads(); }
    if (tid==0) g_lossc_b[b] = red[0];
}

// ---------------- kernel F: final deterministic reductions ----------------
__global__ void kF(float* __restrict__ out, int out_size){
    int tid = threadIdx.x;
    __shared__ float red[256];
    __shared__ int  ired[256];
    __shared__ float s_ll, s_lm, s_lcf;
    float s = 0.f;
    for (int i=tid; i<NBLK_D; i+=256) s += g_part_l[i];
    red[tid]=s; __syncthreads();
    for (int st=128;st>0;st>>=1){ if(tid<st) red[tid]+=red[tid+st]; __syncthreads(); }
    if (tid==0) s_ll = red[0];
    __syncthreads();
    s = 0.f;
    for (int i=tid; i<NBLK_D; i+=256) s += g_part_lm[i];
    red[tid]=s; __syncthreads();
    for (int st=128;st>0;st>>=1){ if(tid<st) red[tid]+=red[tid+st]; __syncthreads(); }
    if (tid==0) s_lm = red[0];
    __syncthreads();
    s = 0.f;
    if (tid < NB) s = g_lossc_b[tid];
    red[tid]=s; __syncthreads();
    for (int st=128;st>0;st>>=1){ if(tid<st) red[tid]+=red[tid+st]; __syncthreads(); }
    if (tid==0) s_lcf = red[0];
    __syncthreads();
    int np = 0;
    if (tid < NB) np = g_numpos[tid];
    ired[tid]=np; __syncthreads();
    for (int st=128;st>0;st>>=1){ if(tid<st) ired[tid]+=ired[tid+st]; __syncthreads(); }
    if (tid==0){
        float N  = fmaxf((float)ired[0], 1.f);
        float N1 = fmaxf((float)g_np1_tot, 1.f);
        if (out_size > 0) out[0] = s_ll  / N;
        if (out_size > 1) out[1] = s_lcf / N;
        if (out_size > 2) out[2] = s_lm  / N1;
    }
}

extern "C" void kernel_launch(void* const* d_in, const int* in_sizes, int n_in,
                              void* d_out, int out_size){
    const float* loc     = (const float*)d_in[0];
    const float* conf    = (const float*)d_in[1];
    const float* landm   = (const float*)d_in[2];
    const float* priors  = (const float*)d_in[3];
    const float* targets = (const float*)d_in[4];
    float* out = (float*)d_out;

    kInit<<<17,256>>>();
    kAB<<<dim3(NCH,NB),256>>>(targets, priors);
    kC<<<NB,NO>>>();
    kD<<<dim3(NCH,NB),256>>>(loc, conf, landm, priors, targets);
    kE<<<NB,256>>>();
    kF<<<1,256>>>(out, out_size);
}

// round 3
// speedup vs baseline: 2.5525x; 1.6315x over previous
#include <cuda_runtime.h>
#include <math.h>

#define NB 64
#define NP 16800
#define NO 64
#define NCH 66               // ceil(NP/256)  (kD grid)
#define NCH2 33              // ceil(NP/512)  (kAB grid, 2 priors/thread)
#define NBLK_D (NB*NCH)
#define THRESH 0.35f
#define NEGPOS 7
#define KE_THREADS 512
#define KE_SMEM (NP*4)

// ---------------- static device scratch ----------------
__device__ float g_bto[(size_t)NB*NP];
__device__ int   g_bti[(size_t)NB*NP];
__device__ float g_lc [(size_t)NB*NP];
__device__ unsigned char g_posm[(size_t)NB*NP];
__device__ unsigned long long g_bpkey[NB*NO];
__device__ float g_part_l [NBLK_D];
__device__ float g_part_lm[NBLK_D];
__device__ int   g_numpos[NB];
__device__ int   g_np1_tot;
__device__ float g_lossc_b[NB];

__device__ __forceinline__ float sl1(float x){
    float a = fabsf(x);
    return (a < 1.f) ? 0.5f*a*a : a - 0.5f;
}
__device__ __forceinline__ unsigned fmap(float f){
    unsigned u = __float_as_uint(f);
    return (u & 0x80000000u) ? ~u : (u | 0x80000000u);
}
__device__ __forceinline__ float funmap(unsigned u){
    return __uint_as_float((u & 0x80000000u) ? (u ^ 0x80000000u) : ~u);
}

// ---------------- init ----------------
__global__ void kInit(){
    int i = blockIdx.x*256 + threadIdx.x;
    if (i < NB*NO) g_bpkey[i] = 0ull;
    if (i < NB)    g_numpos[i] = 0;
    if (i == 0)    g_np1_tot = 0;
}

// ---------------- fused kernel AB: 2 priors per thread ----------------
__global__ void kAB(const float* __restrict__ targets, const float* __restrict__ priors){
    int b   = blockIdx.y;
    int tid = threadIdx.x;
    int p0  = blockIdx.x*512 + tid;      // always < NP (max 16639)
    int p1  = p0 + 256;
    bool v1ok = (p1 < NP);

    __shared__ float4 sbox[NO];
    __shared__ float  sarea[NO];
    if (tid < NO){
        const float* tr = targets + ((size_t)b*NO + tid)*15;
        float x1=tr[0], y1=tr[1], x2=tr[2], y2=tr[3];
        sbox[tid] = make_float4(x1,y1,x2,y2);
        sarea[tid] = (x2-x1)*(y2-y1);
    }
    __syncthreads();

    float4 prA = ((const float4*)priors)[p0];
    float4 prB = ((const float4*)priors)[v1ok ? p1 : 0];
    float ax1 = prA.x - prA.z*0.5f, ay1 = prA.y - prA.w*0.5f;
    float ax2 = prA.x + prA.z*0.5f, ay2 = prA.y + prA.w*0.5f;
    float aa  = (ax2-ax1)*(ay2-ay1);
    float bx1 = prB.x - prB.z*0.5f, by1 = prB.y - prB.w*0.5f;
    float bx2 = prB.x + prB.z*0.5f, by2 = prB.y + prB.w*0.5f;
    float ba  = (bx2-bx1)*(by2-by1);

    float best0 = -1.f, best1 = -1.f;
    int bt0 = 0, bt1 = 0;
    int lane = tid & 31;
    unsigned long long* keyrow = g_bpkey + b*NO;

    #pragma unroll 4
    for (int t = 0; t < NO; ++t){
        float4 tb = sbox[t];
        float  ta = sarea[t];
        // prior 0
        float w0 = fmaxf(fminf(tb.z,ax2) - fmaxf(tb.x,ax1), 0.f);
        float h0 = fmaxf(fminf(tb.w,ay2) - fmaxf(tb.y,ay1), 0.f);
        float i0 = w0*h0;
        float v0 = __fdividef(i0, ta + aa - i0);
        if (v0 > best0){ best0 = v0; bt0 = t; }
        // prior 1
        float w1 = fmaxf(fminf(tb.z,bx2) - fmaxf(tb.x,bx1), 0.f);
        float h1 = fmaxf(fminf(tb.w,by2) - fmaxf(tb.y,by1), 0.f);
        float i1 = w1*h1;
        float v1 = __fdividef(i1, ta + ba - i1);
        if (v1 > best1){ best1 = v1; bt1 = t; }
        // warp max over both prior groups (IoU >= 0 so float bits are order-monotone)
        unsigned u0 = __float_as_uint(v0);
        unsigned u1 = v1ok ? __float_as_uint(v1) : 0u;
        unsigned um = __reduce_max_sync(0xffffffffu, u0 > u1 ? u0 : u1);
        unsigned m0 = __ballot_sync(0xffffffffu, u0 == um);
        unsigned m1 = __ballot_sync(0xffffffffu, u1 == um);
        // first-max: all p0 in this warp < all p1, so prefer group 0
        bool iam = m0 ? (lane == __ffs(m0)-1) : (lane == __ffs(m1)-1);
        if (iam){
            int pw = m0 ? p0 : p1;
            unsigned long long key = ((unsigned long long)um << 32) | (unsigned)(~pw);
            atomicMax(&keyrow[t], key);
        }
    }
    size_t ip = (size_t)b*NP + p0;
    g_bto[ip] = best0; g_bti[ip] = bt0;
    if (v1ok){ g_bto[ip+256] = best1; g_bti[ip+256] = bt1; }
}

// ---------------- kernel C: parallel last-writer-wins scatter ----------------
__global__ void kC(){
    int b = blockIdx.x, j = threadIdx.x;
    __shared__ int sp[NO];
    unsigned long long key = g_bpkey[b*NO + j];
    int   pidx = (int)(~(unsigned)key);
    float bpo  = __uint_as_float((unsigned)(key >> 32));
    sp[j] = pidx;
    __syncthreads();
    bool win = true;
    for (int j2 = j+1; j2 < NO; ++j2) if (sp[j2] == pidx) win = false;
    if (win){
        size_t ip = (size_t)b*NP + pidx;
        g_bti[ip] = j;
        if (bpo >= 0.2f) g_bto[ip] = 2.0f;
    }
}

// ---------------- kernel D ----------------
__global__ void kD(const float* __restrict__ loc, const float* __restrict__ conf,
                   const float* __restrict__ landm, const float* __restrict__ priors,
                   const float* __restrict__ targets){
    int b = blockIdx.y;
    int p = blockIdx.x*256 + threadIdx.x;
    int tid = threadIdx.x;
    float ll=0.f, llm=0.f; int cnt=0;     // cnt = cp | (cp1<<16)
    if (p < NP){
        size_t ip = (size_t)b*NP + p;
        int   t   = g_bti[ip];
        float bto = g_bto[ip];
        const float* tr = targets + ((size_t)b*NO + t)*15;
        float label = tr[14];
        float cf = (bto < THRESH) ? 0.f : label;
        bool pos  = (cf != 0.f);
        bool pos1 = (cf > 0.f);
        float2 c = ((const float2*)conf)[ip];
        // lse - gathered = log(1 + exp(other - gathered)), stabilized
        float d = pos ? (c.x - c.y) : (c.y - c.x);
        float lc = fmaxf(d, 0.f) + __logf(1.f + __expf(-fabsf(d)));
        g_lc[ip]   = lc;
        g_posm[ip] = pos ? 1 : 0;
        if (pos){
            cnt = 1;
            float4 pr = ((const float4*)priors)[p];
            float pcx=pr.x, pcy=pr.y, pw=pr.z, ph=pr.w;
            float x1=tr[0], y1=tr[1], x2=tr[2], y2=tr[3];
            float iw = __fdividef(1.f, 0.1f*pw);
            float ih = __fdividef(1.f, 0.1f*ph);
            float gcx = ((x1+x2)*0.5f - pcx) * iw;
            float gcy = ((y1+y2)*0.5f - pcy) * ih;
            float gw  = __logf((x2-x1)/pw) * 5.f;
            float gh  = __logf((y2-y1)/ph) * 5.f;
            float4 lr = ((const float4*)loc)[ip];
            ll = sl1(lr.x-gcx) + sl1(lr.y-gcy) + sl1(lr.z-gw) + sl1(lr.w-gh);
            if (pos1){
                cnt |= (1<<16);
                const float* ld = landm + ip*10;
                #pragma unroll
                for (int i=0;i<5;++i){
                    float gx = (tr[4+2*i] - pcx)*iw;
                    float gy = (tr[5+2*i] - pcy)*ih;
                    llm += sl1(ld[2*i]-gx) + sl1(ld[2*i+1]-gy);
                }
            }
        }
    }
    // warp reductions, fixed order
    #pragma unroll
    for (int o=16;o>0;o>>=1){
        ll  += __shfl_xor_sync(0xffffffffu, ll,  o);
        llm += __shfl_xor_sync(0xffffffffu, llm, o);
        cnt += __shfl_xor_sync(0xffffffffu, cnt, o);
    }
    __shared__ float sll[8], sllm[8];
    __shared__ int   scnt[8];
    int w = tid >> 5;
    if ((tid & 31) == 0){ sll[w]=ll; sllm[w]=llm; scnt[w]=cnt; }
    __syncthreads();
    if (tid == 0){
        float a=0.f, m=0.f; int cc=0;
        #pragma unroll
        for (int i=0;i<8;++i){ a+=sll[i]; m+=sllm[i]; cc+=scnt[i]; }
        g_part_l [blockIdx.y*NCH + blockIdx.x] = a;
        g_part_lm[blockIdx.y*NCH + blockIdx.x] = m;
        atomicAdd(&g_numpos[b], cc & 0xFFFF);
        atomicAdd(&g_np1_tot, cc >> 16);
    }
}

// ---------------- kernel E: smem-cached radix top-K + masked sum ----------------
__global__ void kE(){
    extern __shared__ unsigned s_u[];          // NP fmap'd values
    int b = blockIdx.x, tid = threadIdx.x;
    __shared__ int hist[256];
    __shared__ unsigned s_prefix, s_pmask;
    __shared__ int s_k, s_cgt;
    int npos = g_numpos[b];
    int K = NEGPOS*npos; if (K > NP-1) K = NP-1;
    const float* lcrow = g_lc + (size_t)b*NP;
    if (tid==0){ s_prefix=0u; s_pmask=0u; s_k=K; s_cgt=0; }
    if (tid < 256) hist[tid]=0;
    __syncthreads();
    // pass 1 (level 3): global -> smem cache + histogram
    for (int i=tid; i<NP; i+=KE_THREADS){
        unsigned u = fmap(lcrow[i]);
        s_u[i] = u;
        atomicAdd(&hist[u >> 24], 1);
    }
    __syncthreads();
    if (K > 0){
        for (int level=3; level>=0; --level){
            if (tid==0){
                int k=s_k, cum=0, bin=255;
                for (; bin>0; --bin){
                    int c = hist[bin];
                    if (cum + c >= k) break;
                    cum += c;
                }
                s_cgt += cum;
                s_k = k - cum;
                s_prefix |= ((unsigned)bin << (level*8));
                s_pmask  |= (0xFFu << (level*8));
            }
            __syncthreads();
            if (level == 0) break;
            if (tid < 256) hist[tid]=0;
            __syncthreads();
            unsigned pm=s_pmask, pf=s_prefix;
            int nl = level-1;
            for (int i=tid; i<NP; i+=KE_THREADS){
                unsigned u = s_u[i];
                if ((u & pm) == pf) atomicAdd(&hist[(u >> (nl*8)) & 0xFF], 1);
            }
            __syncthreads();
        }
    }
    unsigned v = s_prefix;
    int extra = K - s_cgt;
    const int chunk = (NP + KE_THREADS - 1)/KE_THREADS;   // 33
    int beg = tid*chunk;
    int end = beg + chunk; if (end > NP) end = NP;
    __shared__ int eqc[KE_THREADS];
    int eq = 0;
    if (K > 0) for (int i=beg;i<end;++i) if (s_u[i]==v) eq++;
    eqc[tid]=eq; __syncthreads();
    if (tid==0){ int acc=0; for (int i=0;i<KE_THREADS;++i){ int tmp=eqc[i]; eqc[i]=acc; acc+=tmp; } }
    __syncthreads();
    int run = eqc[tid];
    const unsigned char* posrow = g_posm + (size_t)b*NP;
    float s = 0.f;
    for (int i=beg; i<end; ++i){
        unsigned u = s_u[i];
        bool inc = (posrow[i] != 0);
        if (K > 0){
            if (u > v) inc = true;
            else if (u == v){ if (run < extra) inc = true; run++; }
        }
        if (inc) s += funmap(u);
    }
    __shared__ float red[KE_THREADS];
    red[tid]=s; __syncthreads();
    for (int st=KE_THREADS/2; st>0; st>>=1){ if(tid<st) red[tid]+=red[tid+st]; __syncthreads(); }
    if (tid==0) g_lossc_b[b] = red[0];
}

// ---------------- kernel F ----------------
__global__ void kF(float* __restrict__ out, int out_size){
    int tid = threadIdx.x;
    __shared__ float red[256];
    __shared__ int  ired[256];
    __shared__ float s_ll, s_lm, s_lcf;
    float s = 0.f;
    for (int i=tid; i<NBLK_D; i+=256) s += g_part_l[i];
    red[tid]=s; __syncthreads();
    for (int st=128;st>0;st>>=1){ if(tid<st) red[tid]+=red[tid+st]; __syncthreads(); }
    if (tid==0) s_ll = red[0];
    __syncthreads();
    s = 0.f;
    for (int i=tid; i<NBLK_D; i+=256) s += g_part_lm[i];
    red[tid]=s; __syncthreads();
    for (int st=128;st>0;st>>=1){ if(tid<st) red[tid]+=red[tid+st]; __syncthreads(); }
    if (tid==0) s_lm = red[0];
    __syncthreads();
    s = 0.f;
    if (tid < NB) s = g_lossc_b[tid];
    red[tid]=s; __syncthreads();
    for (int st=128;st>0;st>>=1){ if(tid<st) red[tid]+=red[tid+st]; __syncthreads(); }
    if (tid==0) s_lcf = red[0];
    __syncthreads();
    int np = 0;
    if (tid < NB) np = g_numpos[tid];
    ired[tid]=np; __syncthreads();
    for (int st=128;st>0;st>>=1){ if(tid<st) ired[tid]+=ired[tid+st]; __syncthreads(); }
    if (tid==0){
        float N  = fmaxf((float)ired[0], 1.f);
        float N1 = fmaxf((float)g_np1_tot, 1.f);
        if (out_size > 0) out[0] = s_ll  / N;
        if (out_size > 1) out[1] = s_lcf / N;
        if (out_size > 2) out[2] = s_lm  / N1;
    }
}

extern "C" void kernel_launch(void* const* d_in, const int* in_sizes, int n_in,
                              void* d_out, int out_size){
    const float* loc     = (const float*)d_in[0];
    const float* conf    = (const float*)d_in[1];
    const float* landm   = (const float*)d_in[2];
    const float* priors  = (const float*)d_in[3];
    const float* targets = (const float*)d_in[4];
    float* out = (float*)d_out;

    cudaFuncSetAttribute(kE, cudaFuncAttributeMaxDynamicSharedMemorySize, KE_SMEM);

    kInit<<<17,256>>>();
    kAB<<<dim3(NCH2,NB),256>>>(targets, priors);
    kC<<<NB,NO>>>();
    kD<<<dim3(NCH,NB),256>>>(loc, conf, landm, priors, targets);
    kE<<<NB,KE_THREADS,KE_SMEM>>>();
    kF<<<1,256>>>(out, out_size);
}

// round 4
// speedup vs baseline: 2.7964x; 1.0956x over previous
#include <cuda_runtime.h>
#include <math.h>

#define NB 64
#define NP 16800
#define NO 64
#define NCH 66               // ceil(NP/256)   (kD grid)
#define NCHA 17              // ceil(NP/1024)  (kAB grid, 4 priors/thread)
#define NBLK_D (NB*NCH)
#define THRESH 0.35f
#define NEGPOS 7
#define KE_THREADS 512
#define KE_SMEM (NP*4)

// ---------------- static device scratch (zero-initialized at load) ----------------
__device__ float g_bto[(size_t)NB*NP];
__device__ int   g_bti[(size_t)NB*NP];
__device__ float g_lc [(size_t)NB*NP];
__device__ unsigned char g_posm[(size_t)NB*NP];
__device__ unsigned long long g_bpkey[NB*NO];
__device__ float g_part_l [NBLK_D];
__device__ float g_part_lm[NBLK_D];
__device__ int   g_numpos[NB];
__device__ int   g_np1_tot;
__device__ float g_lossc_b[NB];

__device__ __forceinline__ float sl1(float x){
    float a = fabsf(x);
    return (a < 1.f) ? 0.5f*a*a : a - 0.5f;
}
__device__ __forceinline__ unsigned fmap(float f){
    unsigned u = __float_as_uint(f);
    return (u & 0x80000000u) ? ~u : (u | 0x80000000u);
}
__device__ __forceinline__ float funmap(unsigned u){
    return __uint_as_float((u & 0x80000000u) ? (u ^ 0x80000000u) : ~u);
}

// ---------------- fused kernel AB: 4 priors per thread ----------------
__global__ void __launch_bounds__(256) kAB(const float* __restrict__ targets,
                                           const float* __restrict__ priors){
    int b   = blockIdx.y;
    int tid = threadIdx.x;
    int pbase = blockIdx.x*1024 + tid;   // group g prior: pbase + g*256

    __shared__ float4 sbox[NO];
    __shared__ float  sarea[NO];
    if (tid < NO){
        const float* tr = targets + ((size_t)b*NO + tid)*15;
        float x1=tr[0], y1=tr[1], x2=tr[2], y2=tr[3];
        sbox[tid] = make_float4(x1,y1,x2,y2);
        sarea[tid] = (x2-x1)*(y2-y1);
    }
    __syncthreads();

    bool val[4];
    float x1c[4], y1c[4], x2c[4], y2c[4], pa[4];
    #pragma unroll
    for (int g=0; g<4; ++g){
        int p = pbase + g*256;
        val[g] = (p < NP);
        float4 pr = ((const float4*)priors)[val[g] ? p : 0];
        x1c[g] = pr.x - pr.z*0.5f; y1c[g] = pr.y - pr.w*0.5f;
        x2c[g] = pr.x + pr.z*0.5f; y2c[g] = pr.y + pr.w*0.5f;
        pa[g]  = (x2c[g]-x1c[g])*(y2c[g]-y1c[g]);
    }

    float bestv[4] = {-1.f,-1.f,-1.f,-1.f};
    int   bt[4]    = {0,0,0,0};
    unsigned long long* keyrow = g_bpkey + b*NO;
    int blkbase = blockIdx.x*1024;

    #pragma unroll 2
    for (int t = 0; t < NO; ++t){
        float4 tb = sbox[t];
        float  ta = sarea[t];
        unsigned u[4];
        #pragma unroll
        for (int g=0; g<4; ++g){
            float w = fmaxf(fminf(tb.z, x2c[g]) - fmaxf(tb.x, x1c[g]), 0.f);
            float h = fmaxf(fminf(tb.w, y2c[g]) - fmaxf(tb.y, y1c[g]), 0.f);
            float inter = w*h;
            float v = __fdividef(inter, ta + pa[g] - inter);
            v = val[g] ? v : -1.f;
            u[g] = val[g] ? __float_as_uint(v) : 0u;   // v>=0 for valid
            if (v > bestv[g]){ bestv[g] = v; bt[g] = t; }
        }
        unsigned um = u[0] > u[1] ? u[0] : u[1];
        unsigned um2 = u[2] > u[3] ? u[2] : u[3];
        um = um > um2 ? um : um2;
        um = __reduce_max_sync(0xffffffffu, um);
        // candidate = in-block prior offset (g*256+tid); smaller = lower p
        int cand = 0x7fffffff;
        #pragma unroll
        for (int g=3; g>=0; --g)
            if (val[g] && u[g] == um) cand = g*256 + tid;
        int cmin = __reduce_min_sync(0xffffffffu, cand);
        if (cand == cmin){
            unsigned long long key = ((unsigned long long)um << 32) | (unsigned)(~(blkbase + cmin));
            atomicMax(&keyrow[t], key);
        }
    }
    size_t ip = (size_t)b*NP + pbase;
    #pragma unroll
    for (int g=0; g<4; ++g)
        if (val[g]){ g_bto[ip + g*256] = bestv[g]; g_bti[ip + g*256] = bt[g]; }
}

// ---------------- kernel C: parallel last-writer-wins scatter + key reset ----------------
__global__ void kC(){
    int b = blockIdx.x, j = threadIdx.x;
    __shared__ int sp[NO];
    unsigned long long key = g_bpkey[b*NO + j];
    g_bpkey[b*NO + j] = 0ull;                   // reset for next replay
    int   pidx = (int)(~(unsigned)key);
    float bpo  = __uint_as_float((unsigned)(key >> 32));
    sp[j] = pidx;
    __syncthreads();
    bool win = true;
    for (int j2 = j+1; j2 < NO; ++j2) if (sp[j2] == pidx) win = false;
    if (win){
        size_t ip = (size_t)b*NP + pidx;
        g_bti[ip] = j;
        if (bpo >= 0.2f) g_bto[ip] = 2.0f;
    }
}

// ---------------- kernel D ----------------
__global__ void kD(const float* __restrict__ loc, const float* __restrict__ conf,
                   const float* __restrict__ landm, const float* __restrict__ priors,
                   const float* __restrict__ targets){
    int b = blockIdx.y;
    int p = blockIdx.x*256 + threadIdx.x;
    int tid = threadIdx.x;
    __shared__ float st[NO*15];
    for (int i=tid; i<NO*15; i+=256) st[i] = targets[(size_t)b*NO*15 + i];
    __syncthreads();
    float ll=0.f, llm=0.f; int cnt=0;     // cnt = cp | (cp1<<16)
    if (p < NP){
        size_t ip = (size_t)b*NP + p;
        int   t   = g_bti[ip];
        float bto = g_bto[ip];
        const float* tr = st + t*15;
        float label = tr[14];
        float cf = (bto < THRESH) ? 0.f : label;
        bool pos  = (cf != 0.f);
        bool pos1 = (cf > 0.f);
        float2 c = ((const float2*)conf)[ip];
        float d = pos ? (c.x - c.y) : (c.y - c.x);
        float lc = fmaxf(d, 0.f) + __logf(1.f + __expf(-fabsf(d)));
        g_lc[ip]   = lc;
        g_posm[ip] = pos ? 1 : 0;
        if (pos){
            cnt = 1;
            float4 pr = ((const float4*)priors)[p];
            float pcx=pr.x, pcy=pr.y, pw=pr.z, ph=pr.w;
            float x1=tr[0], y1=tr[1], x2=tr[2], y2=tr[3];
            float iw = __fdividef(1.f, 0.1f*pw);
            float ih = __fdividef(1.f, 0.1f*ph);
            float gcx = ((x1+x2)*0.5f - pcx) * iw;
            float gcy = ((y1+y2)*0.5f - pcy) * ih;
            float gw  = __logf((x2-x1)/pw) * 5.f;
            float gh  = __logf((y2-y1)/ph) * 5.f;
            float4 lr = ((const float4*)loc)[ip];
            ll = sl1(lr.x-gcx) + sl1(lr.y-gcy) + sl1(lr.z-gw) + sl1(lr.w-gh);
            if (pos1){
                cnt |= (1<<16);
                const float2* ld2 = (const float2*)(landm + ip*10);
                #pragma unroll
                for (int i=0;i<5;++i){
                    float2 lv = ld2[i];
                    float gx = (tr[4+2*i] - pcx)*iw;
                    float gy = (tr[5+2*i] - pcy)*ih;
                    llm += sl1(lv.x-gx) + sl1(lv.y-gy);
                }
            }
        }
    }
    #pragma unroll
    for (int o=16;o>0;o>>=1){
        ll  += __shfl_xor_sync(0xffffffffu, ll,  o);
        llm += __shfl_xor_sync(0xffffffffu, llm, o);
        cnt += __shfl_xor_sync(0xffffffffu, cnt, o);
    }
    __shared__ float sll[8], sllm[8];
    __shared__ int   scnt[8];
    int w = tid >> 5;
    if ((tid & 31) == 0){ sll[w]=ll; sllm[w]=llm; scnt[w]=cnt; }
    __syncthreads();
    if (tid == 0){
        float a=0.f, m=0.f; int cc=0;
        #pragma unroll
        for (int i=0;i<8;++i){ a+=sll[i]; m+=sllm[i]; cc+=scnt[i]; }
        g_part_l [blockIdx.y*NCH + blockIdx.x] = a;
        g_part_lm[blockIdx.y*NCH + blockIdx.x] = m;
        atomicAdd(&g_numpos[b], cc & 0xFFFF);
        atomicAdd(&g_np1_tot, cc >> 16);
    }
}

// ---------------- kernel E: smem-cached radix top-K + masked sum ----------------
__global__ void kE(){
    extern __shared__ unsigned s_u[];          // NP fmap'd values
    int b = blockIdx.x, tid = threadIdx.x;
    int lane = tid & 31, wid = tid >> 5;
    __shared__ int hist[256];
    __shared__ unsigned s_prefix, s_pmask;
    __shared__ int s_k, s_cgt;
    int npos = g_numpos[b];
    int K = NEGPOS*npos; if (K > NP-1) K = NP-1;
    const float* lcrow = g_lc + (size_t)b*NP;
    if (tid==0){ s_prefix=0u; s_pmask=0u; s_k=K; s_cgt=0; }
    if (tid < 256) hist[tid]=0;
    __syncthreads();
    // pass 1 (level 3): global -> smem cache + histogram
    for (int i=tid; i<NP; i+=KE_THREADS){
        unsigned u = fmap(lcrow[i]);
        s_u[i] = u;
        atomicAdd(&hist[u >> 24], 1);
    }
    __syncthreads();
    if (K > 0){
        for (int level=3; level>=0; --level){
            // warp-0 parallel selection: largest bin with suffix_incl >= k
            if (wid == 0){
                int k = s_k;
                int h[8]; int lsum = 0;
                #pragma unroll
                for (int i=0;i<8;++i){ h[i] = hist[lane*8+i]; lsum += h[i]; }
                // suffix-inclusive sum over lanes (higher lanes = higher bins)
                int S = lsum;
                #pragma unroll
                for (int o=1;o<32;o<<=1){
                    int v = __shfl_down_sync(0xffffffffu, S, o);
                    if (lane + o < 32) S += v;
                }
                int above = S - lsum;                 // sum of bins in higher lanes
                int best = -1, bestSuff = 0;
                int suff = above;
                #pragma unroll
                for (int i=7;i>=0;--i){
                    suff += h[i];
                    if (best < 0 && suff >= k){ best = lane*8 + i; bestSuff = suff; }
                }
                int m = __reduce_max_sync(0xffffffffu, best);
                if (best == m && m >= 0){
                    int cum = bestSuff - h[m & 7];    // suffixGT(m)
                    s_cgt += cum;
                    s_k = k - cum;
                    s_prefix |= ((unsigned)m << (level*8));
                    s_pmask  |= (0xFFu << (level*8));
                }
            }
            __syncthreads();
            if (level == 0) break;
            if (tid < 256) hist[tid]=0;
            __syncthreads();
            unsigned pm=s_pmask, pf=s_prefix;
            int nl = level-1;
            for (int i=tid; i<NP; i+=KE_THREADS){
                unsigned u = s_u[i];
                if ((u & pm) == pf) atomicAdd(&hist[(u >> (nl*8)) & 0xFF], 1);
            }
            __syncthreads();
        }
    }
    unsigned v = s_prefix;
    int extra = K - s_cgt;
    const int chunk = (NP + KE_THREADS - 1)/KE_THREADS;   // 33
    int beg = tid*chunk;
    int end = beg + chunk; if (end > NP) end = NP;
    int eq = 0;
    if (K > 0) for (int i=beg;i<end;++i) if (s_u[i]==v) eq++;
    // hierarchical exclusive scan of eq over 512 threads
    int sc = eq;
    #pragma unroll
    for (int o=1;o<32;o<<=1){
        int t2 = __shfl_up_sync(0xffffffffu, sc, o);
        if (lane >= o) sc += t2;
    }
    __shared__ int wsum[16];
    if (lane == 31) wsum[wid] = sc;
    __syncthreads();
    if (tid == 0){
        int acc = 0;
        #pragma unroll
        for (int i=0;i<16;++i){ int tmp = wsum[i]; wsum[i] = acc; acc += tmp; }
    }
    __syncthreads();
    int run = wsum[wid] + (sc - eq);
    const unsigned char* posrow = g_posm + (size_t)b*NP;
    float s = 0.f;
    for (int i=beg; i<end; ++i){
        unsigned u = s_u[i];
        bool inc = (posrow[i] != 0);
        if (K > 0){
            if (u > v) inc = true;
            else if (u == v){ if (run < extra) inc = true; run++; }
        }
        if (inc) s += funmap(u);
    }
    #pragma unroll
    for (int o=16;o>0;o>>=1) s += __shfl_xor_sync(0xffffffffu, s, o);
    __shared__ float fred[16];
    if (lane == 0) fred[wid] = s;
    __syncthreads();
    if (tid == 0){
        float a = 0.f;
        #pragma unroll
        for (int i=0;i<16;++i) a += fred[i];
        g_lossc_b[b] = a;
    }
}

// ---------------- kernel F: final reductions + state reset ----------------
__global__ void kF(float* __restrict__ out, int out_size){
    int tid = threadIdx.x;
    __shared__ float red[256];
    __shared__ int  ired[256];
    __shared__ float s_ll, s_lm, s_lcf;
    float s = 0.f;
    for (int i=tid; i<NBLK_D; i+=256) s += g_part_l[i];
    red[tid]=s; __syncthreads();
    for (int st=128;st>0;st>>=1){ if(tid<st) red[tid]+=red[tid+st]; __syncthreads(); }
    if (tid==0) s_ll = red[0];
    __syncthreads();
    s = 0.f;
    for (int i=tid; i<NBLK_D; i+=256) s += g_part_lm[i];
    red[tid]=s; __syncthreads();
    for (int st=128;st>0;st>>=1){ if(tid<st) red[tid]+=red[tid+st]; __syncthreads(); }
    if (tid==0) s_lm = red[0];
    __syncthreads();
    s = 0.f;
    if (tid < NB) s = g_lossc_b[tid];
    red[tid]=s; __syncthreads();
    for (int st=128;st>0;st>>=1){ if(tid<st) red[tid]+=red[tid+st]; __syncthreads(); }
    if (tid==0) s_lcf = red[0];
    __syncthreads();
    int np = 0;
    if (tid < NB) np = g_numpos[tid];
    ired[tid]=np; __syncthreads();
    for (int st=128;st>0;st>>=1){ if(tid<st) ired[tid]+=ired[tid+st]; __syncthreads(); }
    if (tid < NB) g_numpos[tid] = 0;          // reset for next replay
    if (tid==0){
        float N  = fmaxf((float)ired[0], 1.f);
        float N1 = fmaxf((float)g_np1_tot, 1.f);
        g_np1_tot = 0;                        // reset for next replay
        if (out_size > 0) out[0] = s_ll  / N;
        if (out_size > 1) out[1] = s_lcf / N;
        if (out_size > 2) out[2] = s_lm  / N1;
    }
}

extern "C" void kernel_launch(void* const* d_in, const int* in_sizes, int n_in,
                              void* d_out, int out_size){
    const float* loc     = (const float*)d_in[0];
    const float* conf    = (const float*)d_in[1];
    const float* landm   = (const float*)d_in[2];
    const float* priors  = (const float*)d_in[3];
    const float* targets = (const float*)d_in[4];
    float* out = (float*)d_out;

    cudaFuncSetAttribute(kE, cudaFuncAttributeMaxDynamicSharedMemorySize, KE_SMEM);

    kAB<<<dim3(NCHA,NB),256>>>(targets, priors);
    kC<<<NB,NO>>>();
    kD<<<dim3(NCH,NB),256>>>(loc, conf, landm, priors, targets);
    kE<<<NB,KE_THREADS,KE_SMEM>>>();
    kF<<<1,256>>>(out, out_size);
}